// round 4
// baseline (speedup 1.0000x reference)
#include <cuda_runtime.h>
#include <math.h>

// Problem shape (fixed by the dataset): x [8, 4096, 1024] fp32
#define SEQ   4096
#define DIM   1024
#define BATCH 8
#define SD4   (SEQ * DIM / 4)   // 1,048,576 float4 per batch slice
#define GRID  592               // 148 SMs * 4 CTAs -> exactly one wave

// Accurate sincos of (p_hi + p_lo), 0 <= p <= ~4096.
// fma-based Cody-Waite reduction mod pi/2, cephes minimax polys on |r|<=pi/4.
// Flag-independent (no libm sinf/cosf -> immune to --use_fast_math).
__device__ __forceinline__ void sincos_acc(float p_hi, float p_lo, float* so, float* co) {
    const float TWO_OVER_PI = 0.6366197723675814f;
    const float C1 =  1.57079637050628662109375f;   // (float)(pi/2)
    const float C2 = -4.3711390001862419e-8f;       // pi/2 - C1

    float q = rintf(p_hi * TWO_OVER_PI);
    int   j = (int)q;                                // 0 .. ~2608, non-negative
    float r = fmaf(q, -C1, p_hi);                    // exact-product fma reduction
    r = fmaf(q, -C2, r);
    r = r + p_lo;

    float z = r * r;

    // sin(r) ~= r + r*z*P(z)
    float sp = -1.9515295891e-4f;
    sp = fmaf(sp, z,  8.3321608736e-3f);
    sp = fmaf(sp, z, -1.6666654611e-1f);
    float sr = fmaf(sp * z, r, r);

    // cos(r) ~= 1 - z/2 + z*z*Q(z)
    float cp =  2.443315711809948e-5f;
    cp = fmaf(cp, z, -1.388731625493765e-3f);
    cp = fmaf(cp, z,  4.166664568298827e-2f);
    float cr = fmaf(cp, z * z, fmaf(-0.5f, z, 1.0f));

    int quad = j & 3;
    float ss = (quad == 0) ? sr : (quad == 1) ?  cr : (quad == 2) ? -sr : -cr;
    float cc = (quad == 0) ? cr : (quad == 1) ? -sr : (quad == 2) ? -cr :  sr;
    *so = ss;
    *co = cc;
}

// Compute the PE float4 for (s, d4): [sin(a0), cos(a0), sin(a1), cos(a1)]
__device__ __forceinline__ float4 pe_vec(unsigned s, unsigned d4) {
    const float pos = (float)s;

    // w_k = 10000^(-k/1024) = 2^(-k*L), L = log2(10000)/1024
    const float L    = 0.012976281620653759f;        // log2(10000)/1024
    const float LN2  = 0.6931471805599453f;
    const float RSTE = 0.9910458562488609f;          // 2^(-L)

    const float k0 = (float)(2u * d4);
    float eh = k0 * L;
    float el = fmaf(k0, L, -eh);                     // exact product tail
    float w0 = exp2f(-eh);
    w0 = fmaf(w0, -el * LN2, w0);                    // w0 *= 2^(-el) ~ (1 - el*ln2)
    float w1 = w0 * RSTE;

    // angle = pos * w as a double-float product
    float p0h = pos * w0;
    float p0l = fmaf(pos, w0, -p0h);
    float p1h = pos * w1;
    float p1l = fmaf(pos, w1, -p1h);

    float s0, c0, s1, c1;
    sincos_acc(p0h, p0l, &s0, &c0);
    sincos_acc(p1h, p1l, &s1, &c1);
    return make_float4(s0, c0, s1, c1);
}

// NO min-blocks cap: let ptxas keep ~64 regs so the 8 loads + 8 address pairs
// stay live simultaneously (full MLP=8 front batch). R3 showed capping regs
// to raise occupancy splits the batch and LOWERS DRAM throughput.
__global__ void __launch_bounds__(256) pe_add_kernel(const float4* __restrict__ x,
                                                     float4* __restrict__ out) {
    const unsigned d4 = threadIdx.x;                  // float4 index along D (D/4 = 256)

    // One-wave persistent grid: each CTA walks s = bid, bid+GRID, bid+2*GRID, ...
    for (unsigned s = blockIdx.x; s < SEQ; s += GRID) {
        const unsigned idx = s * 256u + d4;

        // Trig first: temps dead before the load batch is issued.
        const float4 pe = pe_vec(s, d4);

        // 8 front-batched streaming loads (MLP = 8), fully coalesced.
        float4 v[BATCH];
#pragma unroll
        for (int b = 0; b < BATCH; ++b)
            v[b] = __ldcs(&x[b * SD4 + idx]);         // evict-first: don't pollute L2

#pragma unroll
        for (int b = 0; b < BATCH; ++b) {
            float4 t = v[b];
            t.x += pe.x; t.y += pe.y; t.z += pe.z; t.w += pe.w;
            __stcs(&out[b * SD4 + idx], t);           // streaming store
        }
    }
}

extern "C" void kernel_launch(void* const* d_in, const int* in_sizes, int n_in,
                              void* d_out, int out_size) {
    const float4* x = (const float4*)d_in[0];
    float4* out = (float4*)d_out;
    pe_add_kernel<<<GRID, 256>>>(x, out);
}

// round 5
// speedup vs baseline: 1.1317x; 1.1317x over previous
#include <cuda_runtime.h>
#include <math.h>

// Problem shape (fixed by the dataset): x [8, 4096, 1024] fp32
#define SEQ   4096
#define DIM   1024
#define BATCH 8
#define SD4   (SEQ * DIM / 4)   // 1,048,576 float4 per batch slice

// Accurate sincos of (p_hi + p_lo), 0 <= p <= ~4096.
// fma-based Cody-Waite reduction mod pi/2, cephes minimax polys on |r|<=pi/4.
// Flag-independent (no libm sinf/cosf -> immune to --use_fast_math).
__device__ __forceinline__ void sincos_acc(float p_hi, float p_lo, float* so, float* co) {
    const float TWO_OVER_PI = 0.6366197723675814f;
    const float C1 =  1.57079637050628662109375f;   // (float)(pi/2)
    const float C2 = -4.3711390001862419e-8f;       // pi/2 - C1

    float q = rintf(p_hi * TWO_OVER_PI);
    int   j = (int)q;                                // 0 .. ~2608, non-negative
    float r = fmaf(q, -C1, p_hi);                    // exact-product fma reduction
    r = fmaf(q, -C2, r);
    r = r + p_lo;

    float z = r * r;

    // sin(r) ~= r + r*z*P(z)
    float sp = -1.9515295891e-4f;
    sp = fmaf(sp, z,  8.3321608736e-3f);
    sp = fmaf(sp, z, -1.6666654611e-1f);
    float sr = fmaf(sp * z, r, r);

    // cos(r) ~= 1 - z/2 + z*z*Q(z)
    float cp =  2.443315711809948e-5f;
    cp = fmaf(cp, z, -1.388731625493765e-3f);
    cp = fmaf(cp, z,  4.166664568298827e-2f);
    float cr = fmaf(cp, z * z, fmaf(-0.5f, z, 1.0f));

    int quad = j & 3;
    float ss = (quad == 0) ? sr : (quad == 1) ?  cr : (quad == 2) ? -sr : -cr;
    float cc = (quad == 0) ? cr : (quad == 1) ? -sr : (quad == 2) ? -cr :  sr;
    *so = ss;
    *co = cc;
}

// Compute the PE float4 for (s, d4): [sin(a0), cos(a0), sin(a1), cos(a1)]
__device__ __forceinline__ float4 pe_vec(unsigned s, unsigned d4) {
    const float pos = (float)s;

    // w_k = 10000^(-k/1024) = 2^(-k*L), L = log2(10000)/1024
    const float L    = 0.012976281620653759f;        // log2(10000)/1024
    const float LN2  = 0.6931471805599453f;
    const float RSTE = 0.9910458562488609f;          // 2^(-L)

    const float k0 = (float)(2u * d4);
    float eh = k0 * L;
    float el = fmaf(k0, L, -eh);                     // exact product tail
    float w0 = exp2f(-eh);
    w0 = fmaf(w0, -el * LN2, w0);                    // w0 *= 2^(-el) ~ (1 - el*ln2)
    float w1 = w0 * RSTE;

    // angle = pos * w as a double-float product
    float p0h = pos * w0;
    float p0l = fmaf(pos, w0, -p0h);
    float p1h = pos * w1;
    float p1l = fmaf(pos, w1, -p1h);

    float s0, c0, s1, c1;
    sincos_acc(p0h, p0l, &s0, &c0);
    sincos_acc(p1h, p1l, &s1, &c1);
    return make_float4(s0, c0, s1, c1);
}

// R2 structure (straight-line, one seq row per CTA, no occupancy cap: the
// 64-reg regime keeps the full 8-wide load batch). NEW vs R2: loads are
// issued BEFORE the trig, so the ~100+cyc sincos chain executes entirely
// under the 577-cyc DRAM latency of the in-flight loads.
__global__ void __launch_bounds__(256) pe_add_kernel(const float4* __restrict__ x,
                                                     float4* __restrict__ out) {
    const unsigned d4  = threadIdx.x;                 // float4 index along D (D/4 = 256)
    const unsigned s   = blockIdx.x;                  // sequence position 0..4095
    const unsigned idx = s * 256u + d4;

    // 8 front-batched streaming loads (MLP = 8), fully coalesced.
    float4 v[BATCH];
#pragma unroll
    for (int b = 0; b < BATCH; ++b)
        v[b] = __ldcs(&x[b * SD4 + idx]);             // evict-first: don't pollute L2

    // Trig computed while the loads are in flight.
    const float4 pe = pe_vec(s, d4);

#pragma unroll
    for (int b = 0; b < BATCH; ++b) {
        float4 t = v[b];
        t.x += pe.x; t.y += pe.y; t.z += pe.z; t.w += pe.w;
        __stcs(&out[b * SD4 + idx], t);               // streaming store
    }
}

extern "C" void kernel_launch(void* const* d_in, const int* in_sizes, int n_in,
                              void* d_out, int out_size) {
    const float4* x = (const float4*)d_in[0];
    float4* out = (float4*)d_out;
    pe_add_kernel<<<SEQ, 256>>>(x, out);
}